// round 3
// baseline (speedup 1.0000x reference)
#include <cuda_runtime.h>
#include <cstdint>

#define BB 32
#define TT_ 256
#define CHL 16
#define CE_ 64
#define HC_ 64
#define HW_ 256
#define EMB_ 300
#define EIN_ 428
#define XS_ 432
#define LL_ 32
#define NROW (BB*TT_)

__device__ float g_char_rep[NROW*128];
__device__ float g_x[NROW*XS_];
__device__ float g_xg[2][NROW*1024];
__device__ float g_hs[NROW*512];
__device__ float g_feats[NROW*LL_];
__device__ unsigned g_cnt[2];
__device__ volatile unsigned g_epoch[2];

__device__ __forceinline__ float sigf(float x) { return 1.0f/(1.0f+__expf(-x)); }
__device__ __forceinline__ float tanh_(float x) {
    x = fmaxf(x, -43.0f);
    float e = __expf(-2.0f*x);
    return (1.0f - e)/(1.0f + e);
}

__global__ void init_kernel() {
    if (threadIdx.x < 2) { g_cnt[threadIdx.x] = 0u; g_epoch[threadIdx.x] = 0u; }
}

// ---------------- char BiLSTM: 8 seqs/block, dir = blockIdx.y ----------------
__global__ void char_lstm_kernel(
    const int* __restrict__ cseq, const float* __restrict__ char_emb,
    const float* __restrict__ Wih_f, const float* __restrict__ Whh_f,
    const float* __restrict__ bih_f, const float* __restrict__ bhh_f,
    const float* __restrict__ Wih_b, const float* __restrict__ Whh_b,
    const float* __restrict__ bih_b, const float* __restrict__ bhh_b)
{
    extern __shared__ float sm[];
    const int P = 257;
    float* WihT = sm;                 // [64][257]
    float* WhhT = WihT + 64*P;        // [64][257]
    float* bsum = WhhT + 64*P;        // [256]
    float* ce   = bsum + 256;         // [8][16][64]
    float* hsm  = ce + 8*16*64;       // [8][64]
    float* csm  = hsm + 512;          // [8][64]
    float* gts  = csm + 512;          // [8][256]

    const int dir = blockIdx.y;
    const float* Wih = dir ? Wih_b : Wih_f;
    const float* Whh = dir ? Whh_b : Whh_f;
    const float* bih = dir ? bih_b : bih_f;
    const float* bhh = dir ? bhh_b : bhh_f;
    const int tid = threadIdx.x;

    for (int u = tid; u < 256*64; u += 256) {
        int g = u >> 6, k = u & 63;
        WihT[k*P + g] = Wih[u];
        WhhT[k*P + g] = Whh[u];
    }
    bsum[tid] = bih[tid] + bhh[tid];
    for (int u = tid; u < 2048; u += 256) {
        int st = u >> 4, k4 = u & 15;
        int s = st >> 4, t = st & 15;
        int ci = cseq[(blockIdx.x*8 + s)*CHL + t];
        ((float4*)ce)[st*16 + k4] = ((const float4*)char_emb)[ci*16 + k4];
    }
    for (int u = tid; u < 512; u += 256) { hsm[u] = 0.f; csm[u] = 0.f; }
    __syncthreads();

    const int g = tid;
    for (int step = 0; step < 16; ++step) {
        int tcur = dir ? (15 - step) : step;
        float acc[8];
        #pragma unroll
        for (int s = 0; s < 8; ++s) acc[s] = bsum[g];
        #pragma unroll 4
        for (int k4 = 0; k4 < 16; ++k4) {
            float w1[4], w2[4];
            #pragma unroll
            for (int j = 0; j < 4; ++j) {
                w1[j] = WihT[(k4*4+j)*P + g];
                w2[j] = WhhT[(k4*4+j)*P + g];
            }
            #pragma unroll
            for (int s = 0; s < 8; ++s) {
                float4 e = ((float4*)ce)[(s*16 + tcur)*16 + k4];
                float4 h = ((float4*)hsm)[s*16 + k4];
                acc[s] += w1[0]*e.x + w1[1]*e.y + w1[2]*e.z + w1[3]*e.w
                        + w2[0]*h.x + w2[1]*h.y + w2[2]*h.z + w2[3]*h.w;
            }
        }
        #pragma unroll
        for (int s = 0; s < 8; ++s) gts[s*256 + g] = acc[s];
        __syncthreads();
        #pragma unroll
        for (int r = 0; r < 2; ++r) {
            int u = tid + r*256;
            int s = u >> 6, j = u & 63;
            float i_ = sigf(gts[s*256 + j]);
            float f_ = sigf(gts[s*256 + 64 + j]);
            float gg = tanh_(gts[s*256 + 128 + j]);
            float o_ = sigf(gts[s*256 + 192 + j]);
            float c = f_*csm[u] + i_*gg;
            csm[u] = c;
            hsm[u] = o_*tanh_(c);
        }
        __syncthreads();
    }
    int off = dir ? 0 : 64;   // [hb, hf]
    #pragma unroll
    for (int r = 0; r < 2; ++r) {
        int u = tid + r*256;
        int s = u >> 6, j = u & 63;
        g_char_rep[(blockIdx.x*8 + s)*128 + off + j] = hsm[u];
    }
}

// ---------------- x = [emb[sentence], char_rep], padded ----------------
__global__ void gather_x_kernel(const int* __restrict__ sentence,
                                const float* __restrict__ emb)
{
    int row = blockIdx.x, tid = threadIdx.x;
    int w = sentence[row];
    for (int k = tid; k < EMB_; k += 128) g_x[row*XS_ + k] = emb[w*EMB_ + k];
    g_x[row*XS_ + EMB_ + tid] = g_char_rep[row*128 + tid];
    if (tid < 4) g_x[row*XS_ + 428 + tid] = 0.f;
}

// ---------------- xg[dir] = x @ Wih^T (64x64 tiles, BK=16) ----------------
__global__ void wih_gemm_kernel(const float* __restrict__ Wf,
                                const float* __restrict__ Wb)
{
    __shared__ float As[16*64];
    __shared__ float Bs[16*64];
    const int dir = blockIdx.z;
    const float* W = dir ? Wb : Wf;
    float* Cout = g_xg[dir];
    const int m0 = blockIdx.x*64, n0 = blockIdx.y*64;
    const int tid = threadIdx.x;
    const int lr = tid >> 2, lc = tid & 3;
    const int tm = tid >> 4, tn = tid & 15;
    float acc[4][4];
    #pragma unroll
    for (int i = 0; i < 4; ++i)
        #pragma unroll
        for (int j = 0; j < 4; ++j) acc[i][j] = 0.f;

    for (int k0 = 0; k0 < XS_; k0 += 16) {
        float4 a = *(const float4*)&g_x[(m0+lr)*XS_ + k0 + lc*4];
        As[(lc*4+0)*64+lr]=a.x; As[(lc*4+1)*64+lr]=a.y;
        As[(lc*4+2)*64+lr]=a.z; As[(lc*4+3)*64+lr]=a.w;
        float4 bv = make_float4(0.f,0.f,0.f,0.f);
        int kk = k0 + lc*4;
        if (kk < EIN_) bv = *(const float4*)&W[(n0+lr)*EIN_ + kk];
        Bs[(lc*4+0)*64+lr]=bv.x; Bs[(lc*4+1)*64+lr]=bv.y;
        Bs[(lc*4+2)*64+lr]=bv.z; Bs[(lc*4+3)*64+lr]=bv.w;
        __syncthreads();
        #pragma unroll
        for (int k = 0; k < 16; ++k) {
            float4 av = ((float4*)&As[k*64])[tm];
            float4 bw = ((float4*)&Bs[k*64])[tn];
            acc[0][0]+=av.x*bw.x; acc[0][1]+=av.x*bw.y; acc[0][2]+=av.x*bw.z; acc[0][3]+=av.x*bw.w;
            acc[1][0]+=av.y*bw.x; acc[1][1]+=av.y*bw.y; acc[1][2]+=av.y*bw.z; acc[1][3]+=av.y*bw.w;
            acc[2][0]+=av.z*bw.x; acc[2][1]+=av.z*bw.y; acc[2][2]+=av.z*bw.z; acc[2][3]+=av.z*bw.w;
            acc[3][0]+=av.w*bw.x; acc[3][1]+=av.w*bw.y; acc[3][2]+=av.w*bw.z; acc[3][3]+=av.w*bw.w;
        }
        __syncthreads();
    }
    #pragma unroll
    for (int i = 0; i < 4; ++i)
        *(float4*)&Cout[(m0+tm*4+i)*1024 + n0 + tn*4] =
            make_float4(acc[i][0], acc[i][1], acc[i][2], acc[i][3]);
}

// ---------------- word BiLSTM: persistent 128 CTAs, global barrier per step ----
__global__ void word_lstm_kernel(
    const float* __restrict__ Whh_f, const float* __restrict__ Whh_b,
    const float* __restrict__ bih_f, const float* __restrict__ bhh_f,
    const float* __restrict__ bih_b, const float* __restrict__ bhh_b)
{
    extern __shared__ float sm[];
    float* W4s   = sm;            // [64 k4][16 gr] x float4
    float* h_s   = W4s + 4096;    // [32][256]
    float* gates = h_s + 8192;    // [32][16]
    float* c_s   = gates + 512;   // [32][4]
    float* bias  = c_s + 128;     // [16]

    const int tid = threadIdx.x;
    const int dir = blockIdx.x >> 6;
    const int p   = blockIdx.x & 63;
    const float* Whh = dir ? Whh_b : Whh_f;
    const float* bi  = dir ? bih_b : bih_f;
    const float* bh  = dir ? bhh_b : bhh_f;
    const float* xg  = g_xg[dir];

    for (int u = tid; u < 1024; u += 256) {
        int k4 = u >> 4, gr = u & 15;
        int grow = (gr >> 2)*256 + p*4 + (gr & 3);
        ((float4*)W4s)[k4*16 + gr] = *(const float4*)&Whh[grow*256 + k4*4];
    }
    if (tid < 16) {
        int grow = (tid >> 2)*256 + p*4 + (tid & 3);
        bias[tid] = bi[grow] + bh[grow];
    }
    if (tid < 128) c_s[tid] = 0.f;
    __syncthreads();

    const int gr = tid & 15, bp = tid >> 4;
    const int grow = (gr >> 2)*256 + p*4 + (gr & 3);

    for (int it = 0; it < 256; ++it) {
        int tcur = dir ? (255 - it) : it;
        if (it == 0) {
            for (int u = tid; u < 8192; u += 256) h_s[u] = 0.f;
        } else {
            int tprev = dir ? (tcur + 1) : (tcur - 1);
            for (int u = tid; u < 2048; u += 256) {
                int b = u >> 6, k4 = u & 63;
                ((float4*)h_s)[b*64 + k4] =
                    __ldcg((const float4*)&g_hs[(b*256 + tprev)*512 + dir*256 + k4*4]);
            }
        }
        __syncthreads();

        int b1 = bp, b2 = bp + 16;
        float a1 = bias[gr] + xg[(b1*256 + tcur)*1024 + grow];
        float a2 = bias[gr] + xg[(b2*256 + tcur)*1024 + grow];
        #pragma unroll 8
        for (int k4 = 0; k4 < 64; ++k4) {
            float4 w  = ((float4*)W4s)[k4*16 + gr];
            float4 hA = ((float4*)h_s)[b1*64 + k4];
            float4 hB = ((float4*)h_s)[b2*64 + k4];
            a1 += w.x*hA.x + w.y*hA.y + w.z*hA.z + w.w*hA.w;
            a2 += w.x*hB.x + w.y*hB.y + w.z*hB.z + w.w*hB.w;
        }
        gates[b1*16 + gr] = a1;
        gates[b2*16 + gr] = a2;
        __syncthreads();

        if (tid < 128) {
            int b = tid >> 2, j2 = tid & 3;
            float i_ = sigf(gates[b*16 + j2]);
            float f_ = sigf(gates[b*16 + 4 + j2]);
            float gg = tanh_(gates[b*16 + 8 + j2]);
            float o_ = sigf(gates[b*16 + 12 + j2]);
            float c = f_*c_s[tid] + i_*gg;
            c_s[tid] = c;
            __stcg(&g_hs[(b*256 + tcur)*512 + dir*256 + p*4 + j2], o_*tanh_(c));
        }
        __threadfence();
        __syncthreads();
        if (tid == 0) {
            unsigned old = atomicAdd(&g_cnt[dir], 1u);
            if (old == (unsigned)(64*(it+1) - 1)) {
                __threadfence();
                g_epoch[dir] = (unsigned)(it + 1);
            }
            while (g_epoch[dir] < (unsigned)(it + 1)) { }
            __threadfence();
        }
        __syncthreads();
    }
}

// ---------------- feats = hs @ projW^T + b ----------------
__global__ void proj_kernel(const float* __restrict__ projW,
                            const float* __restrict__ projb)
{
    extern __shared__ float sm[];
    float* pw = sm;               // [512][33]
    float* hr = pw + 512*33;      // [8][512]
    const int tid = threadIdx.x;
    for (int u = tid; u < 32*512; u += 256) {
        int l = u >> 9, k = u & 511;
        pw[k*33 + l] = projW[u];
    }
    int row0 = blockIdx.x*8;
    for (int u = tid; u < 1024; u += 256)
        ((float4*)hr)[u] = ((const float4*)&g_hs[row0*512])[u];
    __syncthreads();

    int r = tid >> 5, l = tid & 31;
    float acc = projb[l];
    #pragma unroll 4
    for (int k4 = 0; k4 < 128; ++k4) {
        float4 h4 = ((float4*)hr)[r*128 + k4];
        acc += h4.x*pw[(k4*4+0)*33 + l] + h4.y*pw[(k4*4+1)*33 + l]
             + h4.z*pw[(k4*4+2)*33 + l] + h4.w*pw[(k4*4+3)*33 + l];
    }
    g_feats[(row0 + r)*32 + l] = acc;
}

// ---------------- viterbi: one warp per batch element ----------------
__global__ void viterbi_kernel(const float* __restrict__ trans, float* __restrict__ out)
{
    __shared__ float fv[32];
    __shared__ float tr[32*33];
    __shared__ unsigned char bpv[256*32];
    const int l = threadIdx.x, b = blockIdx.x;
    for (int u = l; u < 1024; u += 32) tr[(u>>5)*33 + (u&31)] = trans[u];
    fv[l] = -10000.0f;
    __syncwarp();

    for (int t = 0; t < 256; ++t) {
        float m = -1e30f; int am = 0;
        #pragma unroll
        for (int pi = 0; pi < 32; ++pi) {
            float s = fv[pi] + tr[l*33 + pi];
            if (s > m) { m = s; am = pi; }
        }
        bpv[t*32 + l] = (unsigned char)am;
        float nf = m + g_feats[(b*256 + t)*32 + l];
        __syncwarp();
        fv[l] = nf;
        __syncwarp();
    }
    if (l == 0) {
        float bm = fv[0]; int bt = 0;
        for (int pi = 1; pi < 32; ++pi) if (fv[pi] > bm) { bm = fv[pi]; bt = pi; }
        out[b] = bm;
        int tag = bt;
        for (int t = 255; t >= 0; --t) {
            out[32 + b*256 + t] = (float)tag;
            tag = (int)bpv[t*32 + tag];
        }
    }
}

extern "C" void kernel_launch(void* const* d_in, const int* in_sizes, int n_in,
                              void* d_out, int out_size)
{
    const int* sent = (const int*)d_in[0];
    const int* cseq = (const int*)d_in[1];
    const float* const* F = (const float* const*)(d_in + 2);
    // F: 0 emb, 1 char_emb, 2..5 cWih_f,cWhh_f,cbih_f,cbhh_f, 6..9 backward,
    //    10..13 wWih_f,wWhh_f,wbih_f,wbhh_f, 14..17 backward, 18 proj_W, 19 proj_b, 20 trans
    float* out = (float*)d_out;

    cudaFuncSetAttribute(char_lstm_kernel, cudaFuncAttributeMaxDynamicSharedMemorySize, 180000);
    cudaFuncSetAttribute(word_lstm_kernel, cudaFuncAttributeMaxDynamicSharedMemorySize, 53000);
    cudaFuncSetAttribute(proj_kernel,      cudaFuncAttributeMaxDynamicSharedMemorySize, 90000);

    init_kernel<<<1, 32>>>();
    char_lstm_kernel<<<dim3(NROW/8, 2), 256, 177664>>>(
        cseq, F[1], F[2], F[3], F[4], F[5], F[6], F[7], F[8], F[9]);
    gather_x_kernel<<<NROW, 128>>>(sent, F[0]);
    wih_gemm_kernel<<<dim3(NROW/64, 1024/64, 2), 256>>>(F[10], F[14]);
    word_lstm_kernel<<<128, 256, 51776>>>(F[11], F[15], F[12], F[13], F[16], F[17]);
    proj_kernel<<<NROW/8, 256, 83968>>>(F[18], F[19]);
    viterbi_kernel<<<BB, 32>>>(F[20], out);
}

// round 4
// speedup vs baseline: 1.0924x; 1.0924x over previous
#include <cuda_runtime.h>
#include <cstdint>

#define BB 32
#define TT_ 256
#define CHL 16
#define CE_ 64
#define HC_ 64
#define HW_ 256
#define EMB_ 300
#define EIN_ 428
#define XS_ 432
#define LL_ 32
#define NROW (BB*TT_)
#define NCHR (NROW*CHL)     // 131072

__device__ float g_char_rep[NROW*128];
__device__ float g_x[NROW*XS_];
__device__ float g_xg[2][NROW*1024];
__device__ float g_cxg[2][NCHR*256];
__device__ float g_hs[NROW*512];
__device__ float g_feats[NROW*LL_];
__device__ unsigned g_cnt[2];
__device__ volatile unsigned g_epoch[2];

__device__ __forceinline__ float sigf(float x) { return 1.0f/(1.0f+__expf(-x)); }
__device__ __forceinline__ float tanh_(float x) {
    x = fmaxf(x, -43.0f);
    float e = __expf(-2.0f*x);
    return (1.0f - e)/(1.0f + e);
}

__global__ void init_kernel() {
    if (threadIdx.x < 2) { g_cnt[threadIdx.x] = 0u; g_epoch[threadIdx.x] = 0u; }
}

// ---- cxg[dir][chr][gate] = char_emb[cseq[chr]] @ Wih^T  (gather-fused GEMM) ----
__global__ void cxg_gemm_kernel(const int* __restrict__ cseq,
                                const float* __restrict__ char_emb,
                                const float* __restrict__ Wf,
                                const float* __restrict__ Wb)
{
    __shared__ float As[16*64];
    __shared__ float Bs[16*64];
    const int dir = blockIdx.z;
    const float* W = dir ? Wb : Wf;
    float* Cout = g_cxg[dir];
    const int m0 = blockIdx.x*64, n0 = blockIdx.y*64;
    const int tid = threadIdx.x;
    const int lr = tid >> 2, lc = tid & 3;
    const int tm = tid >> 4, tn = tid & 15;
    const int ci = cseq[m0 + lr];

    float acc[4][4];
    #pragma unroll
    for (int i = 0; i < 4; ++i)
        #pragma unroll
        for (int j = 0; j < 4; ++j) acc[i][j] = 0.f;

    #pragma unroll
    for (int k0 = 0; k0 < 64; k0 += 16) {
        float4 a = ((const float4*)char_emb)[ci*16 + (k0>>2) + lc];
        As[(lc*4+0)*64+lr]=a.x; As[(lc*4+1)*64+lr]=a.y;
        As[(lc*4+2)*64+lr]=a.z; As[(lc*4+3)*64+lr]=a.w;
        float4 bv = *(const float4*)&W[(n0+lr)*64 + k0 + lc*4];
        Bs[(lc*4+0)*64+lr]=bv.x; Bs[(lc*4+1)*64+lr]=bv.y;
        Bs[(lc*4+2)*64+lr]=bv.z; Bs[(lc*4+3)*64+lr]=bv.w;
        __syncthreads();
        #pragma unroll
        for (int k = 0; k < 16; ++k) {
            float4 av = ((float4*)&As[k*64])[tm];
            float4 bw = ((float4*)&Bs[k*64])[tn];
            acc[0][0]+=av.x*bw.x; acc[0][1]+=av.x*bw.y; acc[0][2]+=av.x*bw.z; acc[0][3]+=av.x*bw.w;
            acc[1][0]+=av.y*bw.x; acc[1][1]+=av.y*bw.y; acc[1][2]+=av.y*bw.z; acc[1][3]+=av.y*bw.w;
            acc[2][0]+=av.z*bw.x; acc[2][1]+=av.z*bw.y; acc[2][2]+=av.z*bw.z; acc[2][3]+=av.z*bw.w;
            acc[3][0]+=av.w*bw.x; acc[3][1]+=av.w*bw.y; acc[3][2]+=av.w*bw.z; acc[3][3]+=av.w*bw.w;
        }
        __syncthreads();
    }
    #pragma unroll
    for (int i = 0; i < 4; ++i)
        *(float4*)&Cout[(m0+tm*4+i)*256 + n0 + tn*4] =
            make_float4(acc[i][0], acc[i][1], acc[i][2], acc[i][3]);
}

// ---- char recurrence: 8 seqs/block, only Whh in smem (2 CTAs/SM) ----
__global__ void char_rec_kernel(
    const float* __restrict__ Whh_f, const float* __restrict__ bih_f, const float* __restrict__ bhh_f,
    const float* __restrict__ Whh_b, const float* __restrict__ bih_b, const float* __restrict__ bhh_b)
{
    extern __shared__ float sm[];
    const int P = 257;
    float* WhhT = sm;                 // [64][257]
    float* bsum = WhhT + 64*P;        // [256]
    float* hsm  = bsum + 256;         // [8][64]
    float* csm  = hsm + 512;          // [8][64]
    float* gts  = csm + 512;          // [8][256]

    const int dir = blockIdx.y;
    const float* Whh = dir ? Whh_b : Whh_f;
    const float* bih = dir ? bih_b : bih_f;
    const float* bhh = dir ? bhh_b : bhh_f;
    const float* cxg = g_cxg[dir];
    const int tid = threadIdx.x;

    for (int u = tid; u < 256*64; u += 256) {
        int g = u >> 6, k = u & 63;
        WhhT[k*P + g] = Whh[u];
    }
    bsum[tid] = bih[tid] + bhh[tid];
    for (int u = tid; u < 512; u += 256) { hsm[u] = 0.f; csm[u] = 0.f; }
    __syncthreads();

    const int g = tid;
    const int seq0 = blockIdx.x*8;
    for (int step = 0; step < 16; ++step) {
        int tcur = dir ? (15 - step) : step;
        float acc[8];
        #pragma unroll
        for (int s = 0; s < 8; ++s)
            acc[s] = bsum[g] + cxg[((seq0 + s)*16 + tcur)*256 + g];
        #pragma unroll 4
        for (int k4 = 0; k4 < 16; ++k4) {
            float w[4];
            #pragma unroll
            for (int j = 0; j < 4; ++j) w[j] = WhhT[(k4*4+j)*P + g];
            #pragma unroll
            for (int s = 0; s < 8; ++s) {
                float4 h = ((float4*)hsm)[s*16 + k4];
                acc[s] += w[0]*h.x + w[1]*h.y + w[2]*h.z + w[3]*h.w;
            }
        }
        #pragma unroll
        for (int s = 0; s < 8; ++s) gts[s*256 + g] = acc[s];
        __syncthreads();
        #pragma unroll
        for (int r = 0; r < 2; ++r) {
            int u = tid + r*256;
            int s = u >> 6, j = u & 63;
            float i_ = sigf(gts[s*256 + j]);
            float f_ = sigf(gts[s*256 + 64 + j]);
            float gg = tanh_(gts[s*256 + 128 + j]);
            float o_ = sigf(gts[s*256 + 192 + j]);
            float c = f_*csm[u] + i_*gg;
            csm[u] = c;
            hsm[u] = o_*tanh_(c);
        }
        __syncthreads();
    }
    int off = dir ? 0 : 64;   // [hb, hf]
    #pragma unroll
    for (int r = 0; r < 2; ++r) {
        int u = tid + r*256;
        int s = u >> 6, j = u & 63;
        g_char_rep[(seq0 + s)*128 + off + j] = hsm[u];
    }
}

// ---- x = [emb[sentence], char_rep], padded to 432 ----
__global__ void gather_x_kernel(const int* __restrict__ sentence,
                                const float* __restrict__ emb)
{
    int row = blockIdx.x, tid = threadIdx.x;
    int w = sentence[row];
    for (int k = tid; k < EMB_; k += 128) g_x[row*XS_ + k] = emb[w*EMB_ + k];
    g_x[row*XS_ + EMB_ + tid] = g_char_rep[row*128 + tid];
    if (tid < 4) g_x[row*XS_ + 428 + tid] = 0.f;
}

// ---- xg[dir] = x @ Wih^T (64x64 tiles, BK=16) ----
__global__ void wih_gemm_kernel(const float* __restrict__ Wf,
                                const float* __restrict__ Wb)
{
    __shared__ float As[16*64];
    __shared__ float Bs[16*64];
    const int dir = blockIdx.z;
    const float* W = dir ? Wb : Wf;
    float* Cout = g_xg[dir];
    const int m0 = blockIdx.x*64, n0 = blockIdx.y*64;
    const int tid = threadIdx.x;
    const int lr = tid >> 2, lc = tid & 3;
    const int tm = tid >> 4, tn = tid & 15;
    float acc[4][4];
    #pragma unroll
    for (int i = 0; i < 4; ++i)
        #pragma unroll
        for (int j = 0; j < 4; ++j) acc[i][j] = 0.f;

    for (int k0 = 0; k0 < XS_; k0 += 16) {
        float4 a = *(const float4*)&g_x[(m0+lr)*XS_ + k0 + lc*4];
        As[(lc*4+0)*64+lr]=a.x; As[(lc*4+1)*64+lr]=a.y;
        As[(lc*4+2)*64+lr]=a.z; As[(lc*4+3)*64+lr]=a.w;
        float4 bv = make_float4(0.f,0.f,0.f,0.f);
        int kk = k0 + lc*4;
        if (kk < EIN_) bv = *(const float4*)&W[(n0+lr)*EIN_ + kk];
        Bs[(lc*4+0)*64+lr]=bv.x; Bs[(lc*4+1)*64+lr]=bv.y;
        Bs[(lc*4+2)*64+lr]=bv.z; Bs[(lc*4+3)*64+lr]=bv.w;
        __syncthreads();
        #pragma unroll
        for (int k = 0; k < 16; ++k) {
            float4 av = ((float4*)&As[k*64])[tm];
            float4 bw = ((float4*)&Bs[k*64])[tn];
            acc[0][0]+=av.x*bw.x; acc[0][1]+=av.x*bw.y; acc[0][2]+=av.x*bw.z; acc[0][3]+=av.x*bw.w;
            acc[1][0]+=av.y*bw.x; acc[1][1]+=av.y*bw.y; acc[1][2]+=av.y*bw.z; acc[1][3]+=av.y*bw.w;
            acc[2][0]+=av.z*bw.x; acc[2][1]+=av.z*bw.y; acc[2][2]+=av.z*bw.z; acc[2][3]+=av.z*bw.w;
            acc[3][0]+=av.w*bw.x; acc[3][1]+=av.w*bw.y; acc[3][2]+=av.w*bw.z; acc[3][3]+=av.w*bw.w;
        }
        __syncthreads();
    }
    #pragma unroll
    for (int i = 0; i < 4; ++i)
        *(float4*)&Cout[(m0+tm*4+i)*1024 + n0 + tn*4] =
            make_float4(acc[i][0], acc[i][1], acc[i][2], acc[i][3]);
}

// ---- word BiLSTM: persistent 128 CTAs, cheap release/acquire barrier ----
__global__ void word_lstm_kernel(
    const float* __restrict__ Whh_f, const float* __restrict__ Whh_b,
    const float* __restrict__ bih_f, const float* __restrict__ bhh_f,
    const float* __restrict__ bih_b, const float* __restrict__ bhh_b)
{
    extern __shared__ float sm[];
    float* W4s   = sm;            // [64 k4][16 gr] x float4
    float* h_s   = W4s + 4096;    // [32][256]
    float* gates = h_s + 8192;    // [32][16]
    float* c_s   = gates + 512;   // [32][4]
    float* bias  = c_s + 128;     // [16]

    const int tid = threadIdx.x;
    const int dir = blockIdx.x >> 6;
    const int p   = blockIdx.x & 63;
    const float* Whh = dir ? Whh_b : Whh_f;
    const float* bi  = dir ? bih_b : bih_f;
    const float* bh  = dir ? bhh_b : bhh_f;
    const float* xg  = g_xg[dir];

    for (int u = tid; u < 1024; u += 256) {
        int k4 = u >> 4, gr = u & 15;
        int grow = (gr >> 2)*256 + p*4 + (gr & 3);
        ((float4*)W4s)[k4*16 + gr] = *(const float4*)&Whh[grow*256 + k4*4];
    }
    if (tid < 16) {
        int grow = (tid >> 2)*256 + p*4 + (tid & 3);
        bias[tid] = bi[grow] + bh[grow];
    }
    if (tid < 128) c_s[tid] = 0.f;
    __syncthreads();

    const int gr = tid & 15, bp = tid >> 4;
    const int grow = (gr >> 2)*256 + p*4 + (gr & 3);
    const int b1 = bp, b2 = bp + 16;

    for (int it = 0; it < 256; ++it) {
        int tcur = dir ? (255 - it) : it;
        // hoist xg loads (gmem) above h-exchange so latency overlaps
        float x1 = xg[(b1*256 + tcur)*1024 + grow];
        float x2 = xg[(b2*256 + tcur)*1024 + grow];

        if (it == 0) {
            for (int u = tid; u < 8192; u += 256) h_s[u] = 0.f;
        } else {
            int tprev = dir ? (tcur + 1) : (tcur - 1);
            for (int u = tid; u < 2048; u += 256) {
                int b = u >> 6, k4 = u & 63;
                ((float4*)h_s)[b*64 + k4] =
                    __ldcg((const float4*)&g_hs[(b*256 + tprev)*512 + dir*256 + k4*4]);
            }
        }
        __syncthreads();

        float a1 = bias[gr] + x1;
        float a2 = bias[gr] + x2;
        #pragma unroll 8
        for (int k4 = 0; k4 < 64; ++k4) {
            float4 w  = ((float4*)W4s)[k4*16 + gr];
            float4 hA = ((float4*)h_s)[b1*64 + k4];
            float4 hB = ((float4*)h_s)[b2*64 + k4];
            a1 += w.x*hA.x + w.y*hA.y + w.z*hA.z + w.w*hA.w;
            a2 += w.x*hB.x + w.y*hB.y + w.z*hB.z + w.w*hB.w;
        }
        gates[b1*16 + gr] = a1;
        gates[b2*16 + gr] = a2;
        __syncthreads();

        if (tid < 128) {
            int b = tid >> 2, j2 = tid & 3;
            float i_ = sigf(gates[b*16 + j2]);
            float f_ = sigf(gates[b*16 + 4 + j2]);
            float gg = tanh_(gates[b*16 + 8 + j2]);
            float o_ = sigf(gates[b*16 + 12 + j2]);
            float c = f_*c_s[tid] + i_*gg;
            c_s[tid] = c;
            __stcg(&g_hs[(b*256 + tcur)*512 + dir*256 + p*4 + j2], o_*tanh_(c));
        }
        __syncthreads();
        // single-thread release/acquire barrier (threadfence-reduction pattern)
        if (tid == 0) {
            __threadfence();
            unsigned old = atomicAdd(&g_cnt[dir], 1u);
            if (old == 64u*(unsigned)(it+1) - 1u) {
                __threadfence();
                g_epoch[dir] = (unsigned)(it + 1);
            }
            while (g_epoch[dir] < (unsigned)(it + 1)) { }
            __threadfence();
        }
        __syncthreads();
    }
}

// ---- feats = hs @ projW^T + b ----
__global__ void proj_kernel(const float* __restrict__ projW,
                            const float* __restrict__ projb)
{
    extern __shared__ float sm[];
    float* pw = sm;               // [512][33]
    float* hr = pw + 512*33;      // [8][512]
    const int tid = threadIdx.x;
    for (int u = tid; u < 32*512; u += 256) {
        int l = u >> 9, k = u & 511;
        pw[k*33 + l] = projW[u];
    }
    int row0 = blockIdx.x*8;
    for (int u = tid; u < 1024; u += 256)
        ((float4*)hr)[u] = ((const float4*)&g_hs[row0*512])[u];
    __syncthreads();

    int r = tid >> 5, l = tid & 31;
    float acc = projb[l];
    #pragma unroll 4
    for (int k4 = 0; k4 < 128; ++k4) {
        float4 h4 = ((float4*)hr)[r*128 + k4];
        acc += h4.x*pw[(k4*4+0)*33 + l] + h4.y*pw[(k4*4+1)*33 + l]
             + h4.z*pw[(k4*4+2)*33 + l] + h4.w*pw[(k4*4+3)*33 + l];
    }
    g_feats[(row0 + r)*32 + l] = acc;
}

// ---- viterbi: one warp per batch element ----
__global__ void viterbi_kernel(const float* __restrict__ trans, float* __restrict__ out)
{
    __shared__ float fv[32];
    __shared__ float tr[32*33];
    __shared__ unsigned char bpv[256*32];
    const int l = threadIdx.x, b = blockIdx.x;
    for (int u = l; u < 1024; u += 32) tr[(u>>5)*33 + (u&31)] = trans[u];
    fv[l] = -10000.0f;
    __syncwarp();

    for (int t = 0; t < 256; ++t) {
        float m = -1e30f; int am = 0;
        #pragma unroll
        for (int pi = 0; pi < 32; ++pi) {
            float s = fv[pi] + tr[l*33 + pi];
            if (s > m) { m = s; am = pi; }
        }
        bpv[t*32 + l] = (unsigned char)am;
        float nf = m + g_feats[(b*256 + t)*32 + l];
        __syncwarp();
        fv[l] = nf;
        __syncwarp();
    }
    if (l == 0) {
        float bm = fv[0]; int bt = 0;
        for (int pi = 1; pi < 32; ++pi) if (fv[pi] > bm) { bm = fv[pi]; bt = pi; }
        out[b] = bm;
        int tag = bt;
        for (int t = 255; t >= 0; --t) {
            out[32 + b*256 + t] = (float)tag;
            tag = (int)bpv[t*32 + tag];
        }
    }
}

extern "C" void kernel_launch(void* const* d_in, const int* in_sizes, int n_in,
                              void* d_out, int out_size)
{
    const int* sent = (const int*)d_in[0];
    const int* cseq = (const int*)d_in[1];
    const float* const* F = (const float* const*)(d_in + 2);
    // F: 0 emb, 1 char_emb, 2..5 cWih_f,cWhh_f,cbih_f,cbhh_f, 6..9 backward,
    //    10..13 wWih_f,wWhh_f,wbih_f,wbhh_f, 14..17 backward, 18 proj_W, 19 proj_b, 20 trans
    float* out = (float*)d_out;

    cudaFuncSetAttribute(char_rec_kernel,  cudaFuncAttributeMaxDynamicSharedMemorySize, 100000);
    cudaFuncSetAttribute(word_lstm_kernel, cudaFuncAttributeMaxDynamicSharedMemorySize, 53000);
    cudaFuncSetAttribute(proj_kernel,      cudaFuncAttributeMaxDynamicSharedMemorySize, 90000);

    init_kernel<<<1, 32>>>();
    cxg_gemm_kernel<<<dim3(NCHR/64, 4, 2), 256>>>(cseq, F[1], F[2], F[6]);
    char_rec_kernel<<<dim3(NROW/8, 2), 256, 79104>>>(F[3], F[4], F[5], F[7], F[8], F[9]);
    gather_x_kernel<<<NROW, 128>>>(sent, F[0]);
    wih_gemm_kernel<<<dim3(NROW/64, 1024/64, 2), 256>>>(F[10], F[14]);
    word_lstm_kernel<<<128, 256, 51776>>>(F[11], F[15], F[12], F[13], F[16], F[17]);
    proj_kernel<<<NROW/8, 256, 83968>>>(F[18], F[19]);
    viterbi_kernel<<<BB, 32>>>(F[20], out);
}